// round 2
// baseline (speedup 1.0000x reference)
#include <cuda_runtime.h>
#include <math.h>

// Problem constants
#define PB 2
#define PL 2048
#define PD 768
#define PH 12
#define PDK 64
#define M1 (PB*PL)        // 4096
#define N1 (3*PD)         // 2304
#define K1 PD             // 768

// Scratch (allocation-free rule: __device__ globals)
__device__ float g_Q[PB*PH*PL*PDK];   // [b][h][l][dk]
__device__ float g_K[PB*PH*PL*PDK];
__device__ float g_V[PB*PH*PL*PDK];
__device__ float g_A[PB*PL*PD];       // attention output, [b][l][h*dk]

// ---------------------------------------------------------------------------
// Tiled SGEMM: C[M,N] = A[M,K] @ B[K,N] + bias
// BM=BN=128, BK=16, 256 threads, 8x8 per thread.
// MODE 0: A = x, epilogue scatters into g_Q/g_K/g_V ([b][h][l][dk] layout)
// MODE 1: A = g_A, epilogue writes C (final output) with bias
// ---------------------------------------------------------------------------
template<int MODE>
__global__ __launch_bounds__(256, 2)
void sgemm_kernel(const float* __restrict__ Ain, const float* __restrict__ Bm,
                  const float* __restrict__ bias, float* __restrict__ C,
                  int M, int N, int K)
{
    __shared__ float As[16][132];   // transposed A tile, padded
    __shared__ float Bs[16][128];

    const float* A = (MODE == 1) ? (const float*)g_A : Ain;

    int tid = threadIdx.x;
    int tm = tid >> 4;          // 0..15
    int tn = tid & 15;          // 0..15
    int m0 = blockIdx.y * 128;
    int n0 = blockIdx.x * 128;

    float acc[8][8];
#pragma unroll
    for (int i = 0; i < 8; i++)
#pragma unroll
        for (int j = 0; j < 8; j++) acc[i][j] = 0.f;

    for (int k0 = 0; k0 < K; k0 += 16) {
        // Load A tile (128 rows x 16 cols), store transposed As[k][m]
#pragma unroll
        for (int jj = 0; jj < 2; jj++) {
            int i = tid + 256 * jj;
            int row = i >> 2;
            int c4  = i & 3;
            float4 a = *(const float4*)(A + (size_t)(m0 + row) * K + k0 + 4 * c4);
            As[4*c4+0][row] = a.x;
            As[4*c4+1][row] = a.y;
            As[4*c4+2][row] = a.z;
            As[4*c4+3][row] = a.w;
        }
        // Load B tile (16 rows x 128 cols)
#pragma unroll
        for (int jj = 0; jj < 2; jj++) {
            int i = tid + 256 * jj;
            int kr = i >> 5;
            int c4 = i & 31;
            *(float4*)(&Bs[kr][4*c4]) =
                *(const float4*)(Bm + (size_t)(k0 + kr) * N + n0 + 4 * c4);
        }
        __syncthreads();

#pragma unroll
        for (int kk = 0; kk < 16; kk++) {
            float af[8], bf[8];
            *(float4*)(af)     = *(const float4*)(&As[kk][tm*8]);
            *(float4*)(af + 4) = *(const float4*)(&As[kk][tm*8 + 4]);
            *(float4*)(bf)     = *(const float4*)(&Bs[kk][tn*8]);
            *(float4*)(bf + 4) = *(const float4*)(&Bs[kk][tn*8 + 4]);
#pragma unroll
            for (int i = 0; i < 8; i++)
#pragma unroll
                for (int j = 0; j < 8; j++)
                    acc[i][j] += af[i] * bf[j];
        }
        __syncthreads();
    }

    if (MODE == 0) {
        // Scatter into Q/K/V with [b][h][l][dk] layout
#pragma unroll
        for (int j = 0; j < 8; j++) {
            int c = n0 + tn * 8 + j;
            float bv = bias[c];
            int which = c / PD;
            int rem = c - which * PD;
            int h = rem >> 6;       // /64
            int dk = rem & 63;
            float* dst = (which == 0) ? g_Q : (which == 1) ? g_K : g_V;
#pragma unroll
            for (int i = 0; i < 8; i++) {
                int r = m0 + tm * 8 + i;
                int b = r >> 11;        // /2048
                int l = r & 2047;
                dst[(((size_t)(b * PH + h)) * PL + l) * PDK + dk] = acc[i][j] + bv;
            }
        }
    } else {
        float4 bv0 = *(const float4*)(bias + n0 + tn * 8);
        float4 bv1 = *(const float4*)(bias + n0 + tn * 8 + 4);
#pragma unroll
        for (int i = 0; i < 8; i++) {
            int r = m0 + tm * 8 + i;
            float4 c0, c1;
            c0.x = acc[i][0] + bv0.x; c0.y = acc[i][1] + bv0.y;
            c0.z = acc[i][2] + bv0.z; c0.w = acc[i][3] + bv0.w;
            c1.x = acc[i][4] + bv1.x; c1.y = acc[i][5] + bv1.y;
            c1.z = acc[i][6] + bv1.z; c1.w = acc[i][7] + bv1.w;
            *(float4*)(C + (size_t)r * N + n0 + tn * 8)     = c0;
            *(float4*)(C + (size_t)r * N + n0 + tn * 8 + 4) = c1;
        }
    }
}

// ---------------------------------------------------------------------------
// Flash attention (causal), fp32.
// Grid: (L/64, B*H). Block: 256 threads (16x16), each thread a 4x4 fragment.
// 64-query tile, iterate 64-key blocks kt = 0..qt (causal skip).
// Smem: Qs (natural), KP (K transposed [d][k], then reused for P [k][q]),
//       Vs (natural [k][d]).  Exactly 48KB static.
// ---------------------------------------------------------------------------
__global__ __launch_bounds__(256, 2)
void attn_kernel()
{
    __shared__ float Qs[64][64];
    __shared__ float KP[64][64];
    __shared__ float Vs[64][64];

    int tid = threadIdx.x;
    int ty = tid >> 4;      // 0..15 -> query rows 4*ty..
    int tx = tid & 15;      // 0..15 -> key/dim cols 4*tx..
    int qt = blockIdx.x;
    int bh = blockIdx.y;

    const float* Qg = g_Q + (size_t)bh * PL * PDK + (size_t)qt * 64 * PDK;
    const float* Kg = g_K + (size_t)bh * PL * PDK;
    const float* Vg = g_V + (size_t)bh * PL * PDK;

    // Load Q tile (64x64), natural layout
#pragma unroll
    for (int jj = 0; jj < 4; jj++) {
        int i = tid + 256 * jj;
        int q = i >> 4;
        int d4 = i & 15;
        *(float4*)(&Qs[q][4*d4]) = *(const float4*)(Qg + q * PDK + 4 * d4);
    }

    float mrow[4], lrow[4], o[4][4];
#pragma unroll
    for (int i = 0; i < 4; i++) {
        mrow[i] = -INFINITY;
        lrow[i] = 0.f;
#pragma unroll
        for (int j = 0; j < 4; j++) o[i][j] = 0.f;
    }

    const int nkt = qt + 1;
    for (int kt = 0; kt < nkt; kt++) {
        __syncthreads();   // prior iter's reads of KP(P)/Vs complete
        // Load K transposed -> KP[d][k]; V natural -> Vs[k][d]
#pragma unroll
        for (int jj = 0; jj < 4; jj++) {
            int i = tid + 256 * jj;
            int kr = i >> 4;
            int d4 = i & 15;
            float4 kv = *(const float4*)(Kg + (size_t)(kt * 64 + kr) * PDK + 4 * d4);
            KP[4*d4+0][kr] = kv.x;
            KP[4*d4+1][kr] = kv.y;
            KP[4*d4+2][kr] = kv.z;
            KP[4*d4+3][kr] = kv.w;
            *(float4*)(&Vs[kr][4*d4]) =
                *(const float4*)(Vg + (size_t)(kt * 64 + kr) * PDK + 4 * d4);
        }
        __syncthreads();

        // S = Q @ K^T  (64x64x64), 4x4 per thread
        float s[4][4];
#pragma unroll
        for (int i = 0; i < 4; i++)
#pragma unroll
            for (int j = 0; j < 4; j++) s[i][j] = 0.f;

#pragma unroll
        for (int d = 0; d < 64; d++) {
            float bf[4];
            *(float4*)bf = *(const float4*)(&KP[d][4*tx]);
            float af[4];
            af[0] = Qs[4*ty+0][d];
            af[1] = Qs[4*ty+1][d];
            af[2] = Qs[4*ty+2][d];
            af[3] = Qs[4*ty+3][d];
#pragma unroll
            for (int i = 0; i < 4; i++)
#pragma unroll
                for (int j = 0; j < 4; j++)
                    s[i][j] += af[i] * bf[j];
        }

        // Scale + causal mask (only the diagonal tile can mask)
        const bool diag = (kt == qt);
#pragma unroll
        for (int i = 0; i < 4; i++)
#pragma unroll
            for (int j = 0; j < 4; j++) {
                float v = s[i][j] * 0.125f;
                if (diag && (4*tx + j) > (4*ty + i)) v = -1e30f;
                s[i][j] = v;
            }

        // Online softmax. Row i is shared by the 16 lanes of the tx-group.
        float alpha[4];
#pragma unroll
        for (int i = 0; i < 4; i++) {
            float rm = fmaxf(fmaxf(s[i][0], s[i][1]), fmaxf(s[i][2], s[i][3]));
#pragma unroll
            for (int off = 8; off > 0; off >>= 1)
                rm = fmaxf(rm, __shfl_xor_sync(0xffffffffu, rm, off));
            float mn = fmaxf(mrow[i], rm);
            alpha[i] = __expf(mrow[i] - mn);
            mrow[i] = mn;
            float rs = 0.f;
#pragma unroll
            for (int j = 0; j < 4; j++) {
                s[i][j] = __expf(s[i][j] - mn);
                rs += s[i][j];
            }
#pragma unroll
            for (int off = 8; off > 0; off >>= 1)
                rs += __shfl_xor_sync(0xffffffffu, rs, off);
            lrow[i] = lrow[i] * alpha[i] + rs;
#pragma unroll
            for (int j = 0; j < 4; j++) o[i][j] *= alpha[i];
        }

        __syncthreads();   // all threads done reading KP as K
        // Store P into KP: KP[k][q]
#pragma unroll
        for (int j = 0; j < 4; j++) {
            float4 pv;
            pv.x = s[0][j]; pv.y = s[1][j]; pv.z = s[2][j]; pv.w = s[3][j];
            *(float4*)(&KP[4*tx + j][4*ty]) = pv;
        }
        __syncthreads();

        // O += P @ V  (64x64x64)
#pragma unroll
        for (int k = 0; k < 64; k++) {
            float af[4], bf[4];
            *(float4*)af = *(const float4*)(&KP[k][4*ty]);
            *(float4*)bf = *(const float4*)(&Vs[k][4*tx]);
#pragma unroll
            for (int i = 0; i < 4; i++)
#pragma unroll
                for (int j = 0; j < 4; j++)
                    o[i][j] += af[i] * bf[j];
        }
    }

    // Normalize and write to g_A: [b][l][h*64 + d]
    int b = bh / PH;
    int h = bh - b * PH;
#pragma unroll
    for (int i = 0; i < 4; i++) {
        float inv = 1.f / lrow[i];
        int q = qt * 64 + 4 * ty + i;
        float4 ov;
        ov.x = o[i][0] * inv;
        ov.y = o[i][1] * inv;
        ov.z = o[i][2] * inv;
        ov.w = o[i][3] * inv;
        *(float4*)(g_A + ((size_t)b * PL + q) * PD + h * PDK + 4 * tx) = ov;
    }
}

// ---------------------------------------------------------------------------
extern "C" void kernel_launch(void* const* d_in, const int* in_sizes, int n_in,
                              void* d_out, int out_size)
{
    const float* x    = (const float*)d_in[0];
    // d_in[1] = additive causal mask — logic implemented directly, unused
    const float* Wqkv = (const float*)d_in[2];
    const float* bqkv = (const float*)d_in[3];
    const float* Wo   = (const float*)d_in[4];
    const float* bo   = (const float*)d_in[5];
    float* out = (float*)d_out;

    // 1) QKV projection: [4096,768] @ [768,2304] -> scattered Q/K/V
    dim3 g1(N1 / 128, M1 / 128);   // (18, 32)
    sgemm_kernel<0><<<g1, 256>>>(x, Wqkv, bqkv, nullptr, M1, N1, K1);

    // 2) Causal flash attention per (b,h), 64-query tiles
    dim3 g2(PL / 64, PB * PH);     // (32, 24)
    attn_kernel<<<g2, 256>>>();

    // 3) Output projection: [4096,768] @ [768,768] + bo -> out
    dim3 g3(PD / 128, M1 / 128);   // (6, 32)
    sgemm_kernel<1><<<g3, 256>>>(nullptr, Wo, bo, out, M1, PD, K1);
}

// round 3
// speedup vs baseline: 1.1207x; 1.1207x over previous
#include <cuda_runtime.h>
#include <math.h>

// Problem constants
#define PB 2
#define PL 2048
#define PD 768
#define PH 12
#define PDK 64
#define M1 (PB*PL)        // 4096
#define N1 (3*PD)         // 2304
#define K1 PD             // 768

// Scratch (allocation-free rule: __device__ globals)
// Q, K stored TRANSPOSED per head: [b][h][dk][l]   (so attention needs no smem transpose)
// V natural: [b][h][l][dk]
__device__ float g_Q[PB*PH*PDK*PL];
__device__ float g_K[PB*PH*PDK*PL];
__device__ float g_V[PB*PH*PL*PDK];
__device__ float g_A[PB*PL*PD];       // attention output, [b][l][h*dk]

__device__ __forceinline__ void cp_async16(void* smem_dst, const void* gmem_src) {
    unsigned sm = (unsigned)__cvta_generic_to_shared(smem_dst);
    asm volatile("cp.async.cg.shared.global [%0], [%1], 16;\n" :: "r"(sm), "l"(gmem_src));
}
__device__ __forceinline__ void cp_async_commit() {
    asm volatile("cp.async.commit_group;\n" ::: "memory");
}
__device__ __forceinline__ void cp_async_wait_all() {
    asm volatile("cp.async.wait_group 0;\n" ::: "memory");
}

// ---------------------------------------------------------------------------
// Tiled SGEMM: C[M,N] = A[M,K] @ B[K,N] + bias
// BM=BN=128, BK=16, 256 threads, 8x8 per thread. Double-buffered:
// B via cp.async, A via register staging (needs transpose in smem).
// MODE 0: A = x, epilogue scatters into g_Q/g_K (transposed) / g_V (natural)
// MODE 1: A = g_A, epilogue writes C (final output) with bias
// ---------------------------------------------------------------------------
template<int MODE>
__global__ __launch_bounds__(256, 2)
void sgemm_kernel(const float* __restrict__ Ain, const float* __restrict__ Bm,
                  const float* __restrict__ bias, float* __restrict__ C,
                  int M, int N, int K)
{
    __shared__ float As[2][16][132];   // transposed A tile, padded
    __shared__ float Bs[2][16][128];

    const float* A = (MODE == 1) ? (const float*)g_A : Ain;

    int tid = threadIdx.x;
    int tm = tid >> 4;          // 0..15
    int tn = tid & 15;          // 0..15
    int m0 = blockIdx.y * 128;
    int n0 = blockIdx.x * 128;

    float acc[8][8];
#pragma unroll
    for (int i = 0; i < 8; i++)
#pragma unroll
        for (int j = 0; j < 8; j++) acc[i][j] = 0.f;

    float4 a_st[2];

    // ---- prologue: stage tile 0 ----
#pragma unroll
    for (int jj = 0; jj < 2; jj++) {
        int i = tid + 256 * jj;
        int row = i >> 2, c4 = i & 3;
        a_st[jj] = *(const float4*)(A + (size_t)(m0 + row) * K + 4 * c4);
    }
#pragma unroll
    for (int jj = 0; jj < 2; jj++) {
        int i = tid + 256 * jj;
        int kr = i >> 5, c4 = i & 31;
        cp_async16(&Bs[0][kr][4 * c4], Bm + (size_t)kr * N + n0 + 4 * c4);
    }
#pragma unroll
    for (int jj = 0; jj < 2; jj++) {
        int i = tid + 256 * jj;
        int row = i >> 2, c4 = i & 3;
        As[0][4*c4+0][row] = a_st[jj].x;
        As[0][4*c4+1][row] = a_st[jj].y;
        As[0][4*c4+2][row] = a_st[jj].z;
        As[0][4*c4+3][row] = a_st[jj].w;
    }
    cp_async_commit();
    cp_async_wait_all();
    __syncthreads();

    const int NIT = K / 16;
    for (int it = 0; it < NIT; it++) {
        int cur = it & 1, nxt = cur ^ 1;
        int k0n = (it + 1) * 16;
        bool has_next = (it + 1) < NIT;

        if (has_next) {
#pragma unroll
            for (int jj = 0; jj < 2; jj++) {
                int i = tid + 256 * jj;
                int row = i >> 2, c4 = i & 3;
                a_st[jj] = *(const float4*)(A + (size_t)(m0 + row) * K + k0n + 4 * c4);
            }
#pragma unroll
            for (int jj = 0; jj < 2; jj++) {
                int i = tid + 256 * jj;
                int kr = i >> 5, c4 = i & 31;
                cp_async16(&Bs[nxt][kr][4 * c4], Bm + (size_t)(k0n + kr) * N + n0 + 4 * c4);
            }
            cp_async_commit();
        }

#pragma unroll
        for (int kk = 0; kk < 16; kk++) {
            float af[8], bf[8];
            *(float4*)(af)     = *(const float4*)(&As[cur][kk][tm*8]);
            *(float4*)(af + 4) = *(const float4*)(&As[cur][kk][tm*8 + 4]);
            *(float4*)(bf)     = *(const float4*)(&Bs[cur][kk][tn*8]);
            *(float4*)(bf + 4) = *(const float4*)(&Bs[cur][kk][tn*8 + 4]);
#pragma unroll
            for (int i = 0; i < 8; i++)
#pragma unroll
                for (int j = 0; j < 8; j++)
                    acc[i][j] += af[i] * bf[j];
        }

        if (has_next) {
#pragma unroll
            for (int jj = 0; jj < 2; jj++) {
                int i = tid + 256 * jj;
                int row = i >> 2, c4 = i & 3;
                As[nxt][4*c4+0][row] = a_st[jj].x;
                As[nxt][4*c4+1][row] = a_st[jj].y;
                As[nxt][4*c4+2][row] = a_st[jj].z;
                As[nxt][4*c4+3][row] = a_st[jj].w;
            }
            cp_async_wait_all();
        }
        __syncthreads();
    }

    if (MODE == 0) {
        // Scatter into Q/K (transposed [b][h][dk][l]) and V (natural)
#pragma unroll
        for (int j = 0; j < 8; j++) {
            int c = n0 + tn * 8 + j;
            float bv = bias[c];
            int which = c / PD;
            int rem = c - which * PD;
            int h = rem >> 6;       // /64
            int dk = rem & 63;
            int r0 = m0 + tm * 8;
            int b = r0 >> 11;       // /2048 (8-row blocks never cross)
            int l0 = r0 & 2047;
            if (which == 2) {
                // V natural: [((b*PH+h)*PL + l)*PDK + dk] -- scalar scatter
#pragma unroll
                for (int i = 0; i < 8; i++)
                    g_V[(((size_t)(b * PH + h)) * PL + l0 + i) * PDK + dk] = acc[i][j] + bv;
            } else {
                // Q/K transposed: contiguous along l -> 2x float4
                float* dst = (which == 0) ? g_Q : g_K;
                float* base = dst + (((size_t)(b * PH + h)) * PDK + dk) * PL + l0;
                float4 c0, c1;
                c0.x = acc[0][j] + bv; c0.y = acc[1][j] + bv;
                c0.z = acc[2][j] + bv; c0.w = acc[3][j] + bv;
                c1.x = acc[4][j] + bv; c1.y = acc[5][j] + bv;
                c1.z = acc[6][j] + bv; c1.w = acc[7][j] + bv;
                *(float4*)(base)     = c0;
                *(float4*)(base + 4) = c1;
            }
        }
    } else {
        float4 bv0 = *(const float4*)(bias + n0 + tn * 8);
        float4 bv1 = *(const float4*)(bias + n0 + tn * 8 + 4);
#pragma unroll
        for (int i = 0; i < 8; i++) {
            int r = m0 + tm * 8 + i;
            float4 c0, c1;
            c0.x = acc[i][0] + bv0.x; c0.y = acc[i][1] + bv0.y;
            c0.z = acc[i][2] + bv0.z; c0.w = acc[i][3] + bv0.w;
            c1.x = acc[i][4] + bv1.x; c1.y = acc[i][5] + bv1.y;
            c1.z = acc[i][6] + bv1.z; c1.w = acc[i][7] + bv1.w;
            *(float4*)(C + (size_t)r * N + n0 + tn * 8)     = c0;
            *(float4*)(C + (size_t)r * N + n0 + tn * 8 + 4) = c1;
        }
    }
}

// ---------------------------------------------------------------------------
// Flash attention (causal), fp32, v2.
// Grid: (L/64, B*H). Block: 128 threads (8x16), each thread an 8x4 fragment.
// Q^T and K^T come pre-transposed from gmem ([dk][l]) -> all smem ops natural.
// Smem: Qt[d][q], KT[d][k] (reused as P[q][k]), Vs[k][d]. 48KB static.
// ---------------------------------------------------------------------------
__global__ __launch_bounds__(128, 4)
void attn_kernel()
{
    __shared__ float Qt[64][64];   // [d][q]
    __shared__ float KT[64][64];   // [d][k], reused as P[q][k]
    __shared__ float Vs[64][64];   // [k][d]

    int tid = threadIdx.x;
    int ty = tid >> 4;      // 0..7  -> query rows 8*ty..
    int tx = tid & 15;      // 0..15 -> key/dim cols 4*tx..
    int qt = blockIdx.x;
    int bh = blockIdx.y;

    const float* Qg = g_Q + (size_t)bh * PDK * PL;  // [d][l]
    const float* Kg = g_K + (size_t)bh * PDK * PL;
    const float* Vg = g_V + (size_t)bh * PL * PDK;  // [l][d]

    // Load Q^T tile: Qt[d][q] <- Qg[d*PL + qt*64 + q]
#pragma unroll
    for (int jj = 0; jj < 8; jj++) {
        int i = tid + 128 * jj;
        int d = i >> 4;
        int c4 = i & 15;
        *(float4*)(&Qt[d][4*c4]) = *(const float4*)(Qg + (size_t)d * PL + qt * 64 + 4 * c4);
    }

    float mrow[8], lrow[8], o[8][4];
#pragma unroll
    for (int i = 0; i < 8; i++) {
        mrow[i] = -INFINITY;
        lrow[i] = 0.f;
#pragma unroll
        for (int j = 0; j < 4; j++) o[i][j] = 0.f;
    }

    const int nkt = qt + 1;
    for (int kt = 0; kt < nkt; kt++) {
        __syncthreads();   // prior iter's reads of KT(P)/Vs complete
        // Load K^T -> KT[d][k]; V natural -> Vs[k][d]
#pragma unroll
        for (int jj = 0; jj < 8; jj++) {
            int i = tid + 128 * jj;
            int d = i >> 4;
            int c4 = i & 15;
            *(float4*)(&KT[d][4*c4]) =
                *(const float4*)(Kg + (size_t)d * PL + kt * 64 + 4 * c4);
            *(float4*)(&Vs[d][4*c4]) =
                *(const float4*)(Vg + (size_t)(kt * 64 + d) * PDK + 4 * c4);
        }
        __syncthreads();

        // S = Q^T' @ K  (64x64, K-dim = 64 head dims), 8x4 per thread
        float s[8][4];
#pragma unroll
        for (int i = 0; i < 8; i++)
#pragma unroll
            for (int j = 0; j < 4; j++) s[i][j] = 0.f;

#pragma unroll
        for (int d0 = 0; d0 < 64; d0 += 2) {
            float bf[2][4], af[2][8];
#pragma unroll
            for (int c = 0; c < 2; c++) {
                *(float4*)(bf[c]) = *(const float4*)(&KT[d0+c][4*tx]);
                *(float4*)(af[c])     = *(const float4*)(&Qt[d0+c][8*ty]);
                *(float4*)(af[c] + 4) = *(const float4*)(&Qt[d0+c][8*ty + 4]);
            }
#pragma unroll
            for (int c = 0; c < 2; c++)
#pragma unroll
                for (int i = 0; i < 8; i++)
#pragma unroll
                    for (int j = 0; j < 4; j++)
                        s[i][j] += af[c][i] * bf[c][j];
        }

        // Scale + causal mask (only diagonal tile masks)
        const bool diag = (kt == qt);
#pragma unroll
        for (int i = 0; i < 8; i++)
#pragma unroll
            for (int j = 0; j < 4; j++) {
                float v = s[i][j] * 0.125f;
                if (diag && (4*tx + j) > (8*ty + i)) v = -1e30f;
                s[i][j] = v;
            }

        // Online softmax; row shared by the 16 tx-lanes (half-warp)
#pragma unroll
        for (int i = 0; i < 8; i++) {
            float rm = fmaxf(fmaxf(s[i][0], s[i][1]), fmaxf(s[i][2], s[i][3]));
#pragma unroll
            for (int off = 8; off > 0; off >>= 1)
                rm = fmaxf(rm, __shfl_xor_sync(0xffffffffu, rm, off));
            float mn = fmaxf(mrow[i], rm);
            float alpha = __expf(mrow[i] - mn);
            mrow[i] = mn;
            float rs = 0.f;
#pragma unroll
            for (int j = 0; j < 4; j++) {
                s[i][j] = __expf(s[i][j] - mn);
                rs += s[i][j];
            }
#pragma unroll
            for (int off = 8; off > 0; off >>= 1)
                rs += __shfl_xor_sync(0xffffffffu, rs, off);
            lrow[i] = lrow[i] * alpha + rs;
#pragma unroll
            for (int j = 0; j < 4; j++) o[i][j] *= alpha;
        }

        __syncthreads();   // all threads done reading KT as K^T
        // Store P natural [q][k] into KT region: float4 per row
#pragma unroll
        for (int i = 0; i < 8; i++) {
            float4 pv;
            pv.x = s[i][0]; pv.y = s[i][1]; pv.z = s[i][2]; pv.w = s[i][3];
            *(float4*)(&KT[8*ty + i][4*tx]) = pv;
        }
        __syncthreads();

        // O += P @ V, k in chunks of 4 (all float4 reads)
#pragma unroll
        for (int kc = 0; kc < 16; kc++) {
            float pf[8][4], vf[4][4];
#pragma unroll
            for (int i = 0; i < 8; i++)
                *(float4*)(pf[i]) = *(const float4*)(&KT[8*ty + i][4*kc]);
#pragma unroll
            for (int c = 0; c < 4; c++)
                *(float4*)(vf[c]) = *(const float4*)(&Vs[4*kc + c][4*tx]);
#pragma unroll
            for (int c = 0; c < 4; c++)
#pragma unroll
                for (int i = 0; i < 8; i++)
#pragma unroll
                    for (int j = 0; j < 4; j++)
                        o[i][j] += pf[i][c] * vf[c][j];
        }
    }

    // Normalize and write to g_A: [b][l][h*64 + d]
    int b = bh / PH;
    int h = bh - b * PH;
#pragma unroll
    for (int i = 0; i < 8; i++) {
        float inv = 1.f / lrow[i];
        int q = qt * 64 + 8 * ty + i;
        float4 ov;
        ov.x = o[i][0] * inv;
        ov.y = o[i][1] * inv;
        ov.z = o[i][2] * inv;
        ov.w = o[i][3] * inv;
        *(float4*)(g_A + ((size_t)b * PL + q) * PD + h * PDK + 4 * tx) = ov;
    }
}

// ---------------------------------------------------------------------------
extern "C" void kernel_launch(void* const* d_in, const int* in_sizes, int n_in,
                              void* d_out, int out_size)
{
    const float* x    = (const float*)d_in[0];
    // d_in[1] = additive causal mask — logic implemented directly, unused
    const float* Wqkv = (const float*)d_in[2];
    const float* bqkv = (const float*)d_in[3];
    const float* Wo   = (const float*)d_in[4];
    const float* bo   = (const float*)d_in[5];
    float* out = (float*)d_out;

    // 1) QKV projection: [4096,768] @ [768,2304] -> Q^T/K^T/V scratch
    dim3 g1(N1 / 128, M1 / 128);   // (18, 32)
    sgemm_kernel<0><<<g1, 256>>>(x, Wqkv, bqkv, nullptr, M1, N1, K1);

    // 2) Causal flash attention per (b,h), 64-query tiles
    dim3 g2(PL / 64, PB * PH);     // (32, 24)
    attn_kernel<<<g2, 128>>>();

    // 3) Output projection: [4096,768] @ [768,768] + bo -> out
    dim3 g3(PD / 128, M1 / 128);   // (6, 32)
    sgemm_kernel<1><<<g3, 256>>>(nullptr, Wo, bo, out, M1, PD, K1);
}